// round 6
// baseline (speedup 1.0000x reference)
#include <cuda_runtime.h>
#include <cstddef>
#include <cstdint>

// Problem constants (fixed by setup_inputs)
#define RB   12
#define LB   32
#define MB   16
#define HHB  32
#define HFB  64
#define EB   132
#define BTOT 64
#define NB_PER 8              // batches per block
#define NGROUP (BTOT/NB_PER)  // 8 groups
#define NBLOCKS (NGROUP*RB)   // 96 blocks = 8 clusters of 12
#define NTHREADS 256          // 8 warps

// padded strides (mod 32 in {4,20} -> conflict-free 8-batch wavefronts)
#define ZSTR  436   // per-batch stride in zsD   (436 % 32 == 20)
#define MSTR  180   // per-batch stride in meanT (180 % 32 == 20)
#define ISTR  36    // per-batch stride in incT/hgT (36 % 32 == 4)
#define HSTR  68    // per-batch stride in hbufT (68 % 32 == 4)

struct __align__(16) SmemLayout {
    unsigned long long mbar[2];
    // weights, row-per-output, padded strides
    float mw2[176*36];     // [(slot*16+m)][k]
    float awT[32*MSTR];    // [l][slot*16+m]
    float mb [176];
    float gsw2[32*36];
    float gcw2[32*36];
    float gsb[32];
    float lw2[64*68];      // [o][i 0..63]
    float lbS[64];
    float ow2[32*68];      // [l][hf]
    float obS[32];
    float wih2[96*36];
    float whh2[96*36];
    float bihS[96];
    float bhhS[96];
    // activations, batch-padded
    float zsD [2][NB_PER*ZSTR];   // [buf][b*ZSTR + r*36 + i]
    float meanT[NB_PER*MSTR];     // [b*MSTR + row]
    float incT [NB_PER*ISTR];     // [b*ISTR + l]
    float hbufT[NB_PER*HSTR];     // [b*HSTR + o]
    float hgT  [NB_PER*ISTR];     // [b*ISTR + j]
    float ghS  [96*NB_PER];       // [row*8 + b]
    float giS  [96*NB_PER];
    int   elist[12];
    int   slist[12];
};

__device__ __forceinline__ float fsig(float x) { return 1.0f / (1.0f + __expf(-x)); }

__device__ __forceinline__ uint32_t smem_u32(const void* p) {
    uint32_t a;
    asm("{ .reg .u64 t; cvta.to.shared.u64 t, %1; cvt.u32.u64 %0, t; }"
        : "=r"(a) : "l"(p));
    return a;
}
__device__ __forceinline__ uint32_t mapa_rank(uint32_t laddr, uint32_t rank) {
    uint32_t r;
    asm("mapa.shared::cluster.u32 %0, %1, %2;" : "=r"(r) : "r"(laddr), "r"(rank));
    return r;
}
__device__ __forceinline__ void st_remote_f32(uint32_t addr, float v) {
    asm volatile("st.shared::cluster.f32 [%0], %1;" :: "r"(addr), "f"(v) : "memory");
}
__device__ __forceinline__ void mbar_arrive_remote(uint32_t addr) {
    asm volatile("mbarrier.arrive.release.cluster.shared::cluster.b64 _, [%0];"
                 :: "r"(addr) : "memory");
}
__device__ __forceinline__ void mbar_init(uint32_t addr, uint32_t cnt) {
    asm volatile("mbarrier.init.shared.b64 [%0], %1;" :: "r"(addr), "r"(cnt) : "memory");
}
__device__ __forceinline__ void mbar_wait(uint32_t addr, uint32_t parity) {
    uint32_t done;
    do {
        asm volatile(
            "{\n\t.reg .pred p;\n\t"
            "mbarrier.try_wait.parity.acquire.cluster.shared::cta.b64 p, [%1], %2, 0x989680;\n\t"
            "selp.b32 %0, 1, 0, p;\n\t}"
            : "=r"(done) : "r"(addr), "r"(parity) : "memory");
    } while (!done);
}
__device__ __forceinline__ void cluster_sync_all() {
    asm volatile("barrier.cluster.arrive.aligned;" ::: "memory");
    asm volatile("barrier.cluster.wait.aligned;" ::: "memory");
}

// dot-32 over float4: 2 accumulators
#define DOT32(acc0, acc1, WP, AP)                                    \
    {                                                                \
        _Pragma("unroll")                                            \
        for (int q = 0; q < 8; q++) {                                \
            float4 x = (WP)[q], a = (AP)[q];                         \
            acc0 = fmaf(x.x, a.x, acc0); acc1 = fmaf(x.y, a.y, acc1);\
            acc0 = fmaf(x.z, a.z, acc0); acc1 = fmaf(x.w, a.w, acc1);\
        }                                                            \
    }

__global__ void __launch_bounds__(NTHREADS, 1) __cluster_dims__(RB, 1, 1)
nv_main_kernel(
    const float* __restrict__ z0,  const float* __restrict__ h0,
    const float* __restrict__ mean_w, const float* __restrict__ mean_b,
    const float* __restrict__ add_w,
    const float* __restrict__ gsw, const float* __restrict__ gsb_g,
    const float* __restrict__ gcw,
    const float* __restrict__ lw,  const float* __restrict__ lb_g,
    const float* __restrict__ ow,  const float* __restrict__ ob_g,
    const float* __restrict__ wih, const float* __restrict__ whh,
    const float* __restrict__ bih_g, const float* __restrict__ bhh_g,
    const int* __restrict__ src_idx, const int* __restrict__ tgt_idx,
    int T,
    float* __restrict__ zt, float* __restrict__ hf, float* __restrict__ ms)
{
    extern __shared__ char smraw[];
    SmemLayout& sm = *reinterpret_cast<SmemLayout*>(smraw);
    const int tid = threadIdx.x;
    const int g = blockIdx.x / RB;
    const int r = blockIdx.x % RB;
    const int b0 = g * NB_PER;

    // ---- incoming-edge list ----
    for (int e = tid; e < EB; e += NTHREADS) {
        if (tgt_idx[e] == r) {
            int s = src_idx[e];
            int slot = (s < r) ? s : s - 1;
            sm.elist[slot] = e;
            sm.slist[slot] = s;
        }
    }
    if (tid < 2) mbar_init(smem_u32(&sm.mbar[tid]), 88);
    __syncthreads();

    // ---- cache weights ----
    for (int idx = tid; idx < 176*32; idx += NTHREADS) {
        int row = idx >> 5, k = idx & 31;
        int slot = row >> 4, m = row & 15;
        sm.mw2[row*36 + k] = mean_w[((size_t)sm.elist[slot]*MB + m)*LB + k];
    }
    for (int idx = tid; idx < 32*176; idx += NTHREADS) {
        int l = idx / 176, em = idx % 176;
        int slot = em >> 4, m = em & 15;
        sm.awT[l*MSTR + em] = add_w[((size_t)sm.elist[slot]*LB + l)*MB + m];
    }
    for (int idx = tid; idx < 176; idx += NTHREADS) {
        int slot = idx >> 4, m = idx & 15;
        sm.mb[idx] = mean_b[sm.elist[slot]*MB + m];
    }
    for (int idx = tid; idx < 32*32; idx += NTHREADS) {
        int o = idx >> 5, i = idx & 31;
        sm.gsw2[o*36 + i] = gsw[((size_t)r*LB + o)*LB + i];
        sm.gcw2[o*36 + i] = gcw[((size_t)r*LB + o)*LB + i];
    }
    if (tid < 32) sm.gsb[tid] = gsb_g[r*LB + tid];
    for (int idx = tid; idx < 64*64; idx += NTHREADS) {
        int o = idx >> 6, i = idx & 63;
        sm.lw2[o*68 + i] = lw[((size_t)r*HFB + o)*(2*LB) + i];
    }
    if (tid < 64) sm.lbS[tid] = lb_g[r*HFB + tid];
    for (int idx = tid; idx < 32*64; idx += NTHREADS) {
        int l = idx >> 6, i = idx & 63;
        sm.ow2[l*68 + i] = ow[((size_t)r*LB + l)*HFB + i];
    }
    if (tid < 32) sm.obS[tid] = ob_g[r*LB + tid];
    for (int idx = tid; idx < 96*32; idx += NTHREADS) {
        int j = idx >> 5, i = idx & 31;
        sm.wih2[j*36 + i] = wih[((size_t)r*96 + j)*LB + i];
        sm.whh2[j*36 + i] = whh[((size_t)r*96 + j)*HHB + i];
    }
    if (tid < 96) { sm.bihS[tid] = bih_g[r*96 + tid]; sm.bhhS[tid] = bhh_g[r*96 + tid]; }

    // ---- init state ----
    for (int idx = tid; idx < NB_PER*RB*LB; idx += NTHREADS) {
        int b = idx / (RB*LB); int rem = idx % (RB*LB);
        int rr = rem >> 5, i = rem & 31;
        sm.zsD[0][b*ZSTR + rr*36 + i] = z0[((size_t)(b0+b)*RB + rr)*LB + i];
    }
    for (int idx = tid; idx < NB_PER*HHB; idx += NTHREADS) {
        int b = idx >> 5, j = idx & 31;
        sm.hgT[b*ISTR + j] = h0[((size_t)(b0+b)*RB + r)*HHB + j];
    }
    __syncthreads();
    cluster_sync_all();

    const int w    = tid >> 5;          // warp 0..7
    const int lane = tid & 31;
    const int osub = lane >> 3;         // 0..3
    const int b    = lane & 7;          // batch slot 0..7

    // ---- DSMEM deltas ----
    const uint32_t smem_base = smem_u32(smraw);
    uint32_t pdelta[11];
    #pragma unroll
    for (int k = 0; k < 11; k++) {
        uint32_t prank = (uint32_t)(k + (k >= r ? 1 : 0));
        pdelta[k] = mapa_rank(smem_base, prank) - smem_base;
    }
    uint32_t laneDelta = 0u;
    #pragma unroll
    for (int k = 0; k < 11; k++)
        if (lane == k) laneDelta = pdelta[k];
    const uint32_t mbar_base = smem_u32(&sm.mbar[0]);
    const uint32_t zoff0 = smem_u32(&sm.zsD[0][0]);
    const uint32_t zoff1 = smem_u32(&sm.zsD[1][0]);

    const int row0 = 4*w + osub;        // this lane's primary row (quad w)

    for (int t = 0; t < T; t++) {
        const int buf = t & 1;
        const float* zb = &sm.zsD[buf][b*ZSTR];

        // ============ S0: own-state (no peer deps) ============
        float4 za[8];
        {
            const float4* zp = (const float4*)&zb[r*36];
            #pragma unroll
            for (int q = 0; q < 8; q++) za[q] = zp[q];
        }
        float gspart, lwz0, lwz1;
        {
            float a0 = sm.gsb[row0], a1 = 0.f;
            const float4* wp = (const float4*)&sm.gsw2[row0*36];
            DOT32(a0, a1, wp, za);
            gspart = a0 + a1;
        }
        {
            float a0 = sm.lbS[row0], a1 = 0.f;
            const float4* wp = (const float4*)&sm.lw2[row0*68];
            DOT32(a0, a1, wp, za);
            lwz0 = a0 + a1;
            const int rowB = row0 + 32;
            float c0 = sm.lbS[rowB], c1 = 0.f;
            const float4* wq = (const float4*)&sm.lw2[rowB*68];
            DOT32(c0, c1, wq, za);
            lwz1 = c0 + c1;
        }
        {
            float4 ha[8];
            const float4* hp = (const float4*)&sm.hgT[b*ISTR];
            #pragma unroll
            for (int q = 0; q < 8; q++) ha[q] = hp[q];
            #pragma unroll
            for (int j = 0; j < 3; j++) {
                const int rr = row0 + 32*j;
                float a0 = sm.bhhS[rr], a1 = 0.f;
                const float4* wp = (const float4*)&sm.whh2[rr*36];
                DOT32(a0, a1, wp, ha);
                sm.ghS[rr*8 + b] = a0 + a1;
            }
        }

        // ============ wait for peers' z(t-1) ============
        if (t > 0)
            mbar_wait(mbar_base + (uint32_t)(((t - 1) & 1) * 8),
                      (uint32_t)(((t - 1) >> 1) & 1));

        // ============ S1: edge means (44 quads over 8 warps) ============
        #pragma unroll
        for (int k = 0; k < 6; k++) {
            const int q = w + 8*k;
            if (q < 44) {
                const int row = 4*q + osub;
                const int s = sm.slist[row >> 4];
                const float4* ap = (const float4*)&zb[s*36];
                const float4* wp = (const float4*)&sm.mw2[row*36];
                float a0 = sm.mb[row], a1 = 0.f;
                DOT32(a0, a1, wp, ap);
                sm.meanT[b*MSTR + row] = a0 + a1;
            }
        }
        __syncthreads();   // B: meanT complete

        // ============ S2: projection -> inc (176-dot per lane) ============
        {
            const float4* ap = (const float4*)&sm.meanT[b*MSTR];
            const float4* wp = (const float4*)&sm.awT[row0*MSTR];
            float a0 = 0.f, a1 = 0.f, a2 = 0.f, a3 = 0.f;
            #pragma unroll
            for (int q = 0; q < 44; q++) {
                float4 x = wp[q], a = ap[q];
                a0 = fmaf(x.x, a.x, a0); a1 = fmaf(x.y, a.y, a1);
                a2 = fmaf(x.z, a.z, a2); a3 = fmaf(x.w, a.w, a3);
            }
            sm.incT[b*ISTR + row0] = (a0 + a1) + (a2 + a3);
        }
        __syncthreads();   // C: incT complete

        // ============ S3: inc-consumers ============
        float4 ia[8];
        {
            const float4* ip = (const float4*)&sm.incT[b*ISTR];
            #pragma unroll
            for (int q = 0; q < 8; q++) ia[q] = ip[q];
        }
        float gate;
        {
            float a0 = gspart, a1 = 0.f;
            const float4* wp = (const float4*)&sm.gcw2[row0*36];
            DOT32(a0, a1, wp, ia);
            gate = fsig(a0 + a1);
        }
        {
            float a0 = lwz0, a1 = 0.f;
            const float4* wp = (const float4*)&sm.lw2[row0*68 + 32];
            DOT32(a0, a1, wp, ia);
            const float v = a0 + a1;
            sm.hbufT[b*HSTR + row0] = v * fsig(v);
            const int rowB = row0 + 32;
            float c0 = lwz1, c1 = 0.f;
            const float4* wq = (const float4*)&sm.lw2[rowB*68 + 32];
            DOT32(c0, c1, wq, ia);
            const float v2 = c0 + c1;
            sm.hbufT[b*HSTR + rowB] = v2 * fsig(v2);
        }
        #pragma unroll
        for (int j = 0; j < 3; j++) {
            const int rr = row0 + 32*j;
            float a0 = sm.bihS[rr], a1 = 0.f;
            const float4* wp = (const float4*)&sm.wih2[rr*36];
            DOT32(a0, a1, wp, ia);
            sm.giS[rr*8 + b] = a0 + a1;
        }
        __syncthreads();   // D: hbufT complete

        // ============ S4: out layer, z update, publish ============
        {
            const float4* ap = (const float4*)&sm.hbufT[b*HSTR];
            const float4* wp = (const float4*)&sm.ow2[row0*68];
            float a0 = sm.obS[row0], a1 = 0.f, a2 = 0.f, a3 = 0.f;
            #pragma unroll
            for (int q = 0; q < 16; q++) {
                float4 x = wp[q], a = ap[q];
                a0 = fmaf(x.x, a.x, a0); a1 = fmaf(x.y, a.y, a1);
                a2 = fmaf(x.z, a.z, a2); a3 = fmaf(x.w, a.w, a3);
            }
            const float target = tanhf((a0 + a1) + (a2 + a3));
            const float zold = zb[r*36 + row0];
            const float znew = fmaf(0.1f * gate, target - zold, zold);

            const uint32_t zoff = (buf ? zoff0 : zoff1);   // next buffer
            const uint32_t zaddr = zoff + 4u*(uint32_t)(b*ZSTR + r*36 + row0);
            sm.zsD[buf ^ 1][b*ZSTR + r*36 + row0] = znew;
            #pragma unroll
            for (int k = 0; k < 11; k++)
                st_remote_f32(zaddr + pdelta[k], znew);
            __syncwarp();
            if (lane < 11)
                mbar_arrive_remote(mbar_base + (uint32_t)((t & 1) * 8) + laneDelta);
        }
        __syncthreads();   // E: local zsD[nxt], giS/ghS settled

        // ============ post: outputs + GRU (off inter-CTA critical path) ========
        // zt: warp w handles batch w
        if (lane < 8) {
            float4 v = *(const float4*)&sm.zsD[buf ^ 1][w*ZSTR + r*36 + lane*4];
            *(float4*)&zt[(((size_t)(b0 + w)*T + t)*RB + r)*LB + lane*4] = v;
        }
        // ms: warp w stores batch w's means
        {
            float* msrow = ms + ((size_t)(b0 + w)*T + t)*(EB*MB);
            #pragma unroll
            for (int j = 0; j < 6; j++) {
                const int idx = j*32 + lane;
                if (idx < 176)
                    msrow[sm.elist[idx >> 4]*MB + (idx & 15)] = sm.meanT[w*MSTR + idx];
            }
        }
        // GRU h-update: row j = row0 (0..31)
        {
            const int j = row0;
            const float gr = fsig(sm.giS[j*8 + b]        + sm.ghS[j*8 + b]);
            const float gz = fsig(sm.giS[(32 + j)*8 + b] + sm.ghS[(32 + j)*8 + b]);
            const float nn = tanhf(fmaf(gr, sm.ghS[(64 + j)*8 + b], sm.giS[(64 + j)*8 + b]));
            const float hold = sm.hgT[b*ISTR + j];
            sm.hgT[b*ISTR + j] = (1.0f - gz)*nn + gz*hold;
        }
        __syncthreads();   // F: hgT/zsD ready for next step
    }

    // final h: warp w stores batch w
    hf[((size_t)(b0 + w)*RB + r)*HHB + lane] = sm.hgT[w*ISTR + lane];

    __syncthreads();
    cluster_sync_all();   // peers may still be writing our smem
}

extern "C" void kernel_launch(void* const* d_in, const int* in_sizes, int n_in,
                              void* d_out, int out_size) {
    const float* z0     = (const float*)d_in[0];
    const float* h0     = (const float*)d_in[1];
    const float* mean_w = (const float*)d_in[2];
    const float* mean_b = (const float*)d_in[3];
    const float* add_w  = (const float*)d_in[4];
    const float* gsw    = (const float*)d_in[5];
    const float* gsb    = (const float*)d_in[6];
    const float* gcw    = (const float*)d_in[7];
    const float* lw     = (const float*)d_in[8];
    const float* lb     = (const float*)d_in[9];
    const float* ow     = (const float*)d_in[10];
    const float* ob     = (const float*)d_in[11];
    const float* wih    = (const float*)d_in[12];
    const float* whh    = (const float*)d_in[13];
    const float* bih    = (const float*)d_in[14];
    const float* bhh    = (const float*)d_in[15];
    const int* src_idx  = (const int*)d_in[16];
    const int* tgt_idx  = (const int*)d_in[17];
    // out_size = B*T*R*L + B*R*Hh + B*T*E*M
    const int per_t = BTOT*RB*LB + BTOT*EB*MB;
    const int T = (out_size - BTOT*RB*HHB) / per_t;

    float* out = (float*)d_out;
    float* zt = out;
    float* hf = zt + (size_t)BTOT * T * RB * LB;
    float* ms = hf + (size_t)BTOT * RB * HHB;

    cudaFuncSetAttribute(nv_main_kernel,
                         cudaFuncAttributeMaxDynamicSharedMemorySize,
                         (int)sizeof(SmemLayout));
    cudaFuncSetAttribute(nv_main_kernel,
                         cudaFuncAttributeNonPortableClusterSizeAllowed, 1);

    nv_main_kernel<<<NBLOCKS, NTHREADS, sizeof(SmemLayout)>>>(
        z0, h0, mean_w, mean_b, add_w, gsw, gsb, gcw, lw, lb, ow, ob,
        wih, whh, bih, bhh, src_idx, tgt_idx, T, zt, hf, ms);
}